// round 15
// baseline (speedup 1.0000x reference)
#include <cuda_runtime.h>
#include <cuda_bf16.h>
#include <cstdint>

static constexpr int NTHR = 128;     // 4 warps: nt = wid (16-col group); rows via mi loop
static constexpr int BT = 32;
static constexpr int T_HIST = 11, T_PRED = 80, BATCH = 8192;
static constexpr int GRID = BATCH / BT;   // 256 -> 2 CTAs on most SMs

// ---- smem byte offsets (per CTA) ----
static constexpr int HB     = 4608;       // one 32x72 bf16 buffer (144B rows)
static constexpr int O_H1HI = 0;          // 2 buffers each
static constexpr int O_H1LO = 9216;
static constexpr int O_H2HI = 18432;
static constexpr int O_H2LO = 27648;
static constexpr int O_WSTG = 36864;      // staging: hi 9216 + lo 9216 (64x72 each)
static constexpr int O_X    = 55296;      // 32 x 22 fp32 = 2816
static constexpr int O_B0   = 58112;
static constexpr int O_B1   = 58368;
static constexpr int O_WX0  = 58624;
static constexpr int O_WX1  = 58880;
static constexpr int O_FCW0 = 59136;
static constexpr int O_FCW1 = 59392;
static constexpr int O_FCB  = 59648;
static constexpr int O_PART = 59664;      // 32 rows x 4 groups x float2 = 1024
static constexpr int SMEM_TOTAL = 60688;  // x2 CTAs = 121376 < 227KB

__device__ __forceinline__ uint32_t smem_u32(const void* p) {
    uint32_t a;
    asm("{\n\t.reg .u64 t;\n\tcvta.to.shared.u64 t, %1;\n\tcvt.u32.u64 %0, t;\n\t}"
        : "=r"(a) : "l"(p));
    return a;
}
__device__ __forceinline__ void ldsm4(uint32_t r[4], uint32_t a) {
    asm volatile("ldmatrix.sync.aligned.m8n8.x4.shared.b16 {%0,%1,%2,%3}, [%4];"
        : "=r"(r[0]), "=r"(r[1]), "=r"(r[2]), "=r"(r[3]) : "r"(a));
}
__device__ __forceinline__ void mma_bf16(float c[4], const uint32_t a[4], const uint32_t b[2]) {
    asm("mma.sync.aligned.m16n8k16.row.col.f32.bf16.bf16.f32 "
        "{%0,%1,%2,%3},{%4,%5,%6,%7},{%8,%9},{%0,%1,%2,%3};"
        : "+f"(c[0]), "+f"(c[1]), "+f"(c[2]), "+f"(c[3])
        : "r"(a[0]), "r"(a[1]), "r"(a[2]), "r"(a[3]), "r"(b[0]), "r"(b[1]));
}
// paired tanh: one shared reciprocal for two values (3 MUFU per pair vs 4)
// tanh(x) = 1 - 2/(e^{2x}+1);  r = 2/(d0*d1);  tanh(x0) = 1 - d1*r
__device__ __forceinline__ void tanh2(float x0, float x1, float& r0, float& r1) {
    float t0 = __expf(2.0f * x0);
    float t1 = __expf(2.0f * x1);
    float d0 = t0 + 1.0f, d1 = t1 + 1.0f;
    float rp = __fdividef(2.0f, d0 * d1);
    r0 = fmaf(-d1, rp, 1.0f);
    r1 = fmaf(-d0, rp, 1.0f);
}
// two fp32 -> packed hi bf16x2 (truncated, via PRMT) + lo bf16x2 (rounded residual)
__device__ __forceinline__ void split2(float f0, float f1, uint32_t& hi, uint32_t& lo) {
    uint32_t u0 = __float_as_uint(f0) & 0xffff0000u;
    uint32_t u1 = __float_as_uint(f1) & 0xffff0000u;
    float l0 = f0 - __uint_as_float(u0);
    float l1 = f1 - __uint_as_float(u1);
    asm("prmt.b32 %0, %1, %2, 0x7632;" : "=r"(hi) : "r"(u0), "r"(u1));
    asm("cvt.rn.bf16x2.f32 %0, %1, %2;" : "=r"(lo) : "f"(l1), "f"(l0));
}

__global__ __launch_bounds__(NTHR, 2)
void rnn_mma_kernel(const float* __restrict__ x,
    const float* __restrict__ eWih0, const float* __restrict__ eWhh0,
    const float* __restrict__ ebih0, const float* __restrict__ ebhh0,
    const float* __restrict__ eWih1, const float* __restrict__ eWhh1,
    const float* __restrict__ ebih1, const float* __restrict__ ebhh1,
    const float* __restrict__ dWih0, const float* __restrict__ dWhh0,
    const float* __restrict__ dbih0, const float* __restrict__ dbhh0,
    const float* __restrict__ dWih1, const float* __restrict__ dWhh1,
    const float* __restrict__ dbih1, const float* __restrict__ dbhh1,
    const float* __restrict__ fcW, const float* __restrict__ fcb,
    float* __restrict__ out)
{
    extern __shared__ __align__(128) char smb[];
    float* smf = (float*)smb;
    const uint32_t sb = smem_u32(smb);
    const int tid  = threadIdx.x;
    const int wid  = tid >> 5, lane = tid & 31;
    const int nt   = wid;                // col group: cols nt*16 .. +15
    const int ln4  = lane >> 2, lm4 = lane & 3;
    const int bg0  = blockIdx.x * BT;
    const uint32_t a_off = (uint32_t)((lane & 15) * 144 + (lane >> 4) * 16);

    // persistent B frags: [0]=W0hi [1]=W0lo [2]=W1hi [3]=W1lo [4]=W2hi [5]=W2lo
    uint32_t bW[6][4][2][2];
    float aL1[2][2][4], aL0[2][2][4];    // [mi][nj][e]
    float q0v[4], q1v[4], p0v[4], p1v[4];

    auto zero_acc = [&]() {
#pragma unroll
        for (int mi = 0; mi < 2; ++mi)
#pragma unroll
        for (int nj = 0; nj < 2; ++nj)
#pragma unroll
        for (int e = 0; e < 4; ++e) { aL1[mi][nj][e] = 0.f; aL0[mi][nj][e] = 0.f; }
    };

    // ---------------- one-time init ----------------
    for (int i = tid; i < 9216; i += NTHR) ((uint32_t*)smb)[i] = 0u;   // zero h buffers
    for (int i = tid; i < BT * 2 * T_HIST; i += NTHR)
        smf[O_X/4 + i] = x[(size_t)bg0 * (2*T_HIST) + i];
    if (tid < 64) { smf[O_FCW0/4 + tid] = fcW[tid]; smf[O_FCW1/4 + tid] = fcW[64 + tid]; }
    if (tid < 2)  { smf[O_FCB/4 + tid] = fcb[tid]; }

    // ---------------- phase setup ----------------
    auto setup_phase = [&](const float* W0, const float* W1, const float* W2,
                           const float* Wih0, const float* bih0, const float* bhh0,
                           const float* bih1, const float* bhh1) {
        const float* Ws[3] = {W0, W1, W2};
        unsigned short* sh = (unsigned short*)(smb + O_WSTG);
        unsigned short* sl = sh + 4608;
#pragma unroll
        for (int w = 0; w < 3; ++w) {
            __syncthreads();
            for (int idx = tid; idx < 4096; idx += NTHR) {
                int k = idx >> 6, j = idx & 63;
                float wv = Ws[w][j*64 + k];            // WT[k][j] = W[j][k]
                uint32_t u = __float_as_uint(wv) & 0xffff0000u;
                __nv_bfloat16 lb = __float2bfloat16(wv - __uint_as_float(u));
                sh[k*72 + j] = (unsigned short)(u >> 16);
                sl[k*72 + j] = *(unsigned short*)&lb;
            }
            __syncthreads();
            int n = nt*16 + ln4;
#pragma unroll
            for (int kc = 0; kc < 4; ++kc)
#pragma unroll
            for (int nj = 0; nj < 2; ++nj) {
                int nn = n + nj*8;
                int k0 = kc*16 + lm4*2;
                bW[2*w][kc][nj][0]   = (uint32_t)sh[k0*72+nn]     | ((uint32_t)sh[(k0+1)*72+nn] << 16);
                bW[2*w][kc][nj][1]   = (uint32_t)sh[(k0+8)*72+nn] | ((uint32_t)sh[(k0+9)*72+nn] << 16);
                bW[2*w+1][kc][nj][0] = (uint32_t)sl[k0*72+nn]     | ((uint32_t)sl[(k0+1)*72+nn] << 16);
                bW[2*w+1][kc][nj][1] = (uint32_t)sl[(k0+8)*72+nn] | ((uint32_t)sl[(k0+9)*72+nn] << 16);
            }
        }
        if (tid < 64) {
            smf[O_WX0/4 + tid] = Wih0[tid*2];
            smf[O_WX1/4 + tid] = Wih0[tid*2 + 1];
            smf[O_B0/4  + tid] = bih0[tid] + bhh0[tid];
            smf[O_B1/4  + tid] = bih1[tid] + bhh1[tid];
        }
        __syncthreads();
    };

    // ---------------- MMA phases ----------------
    auto run_mma = [&](int b1, int b2, bool with_l0) {
        const uint32_t h1h = sb + O_H1HI + b1*HB;
        const uint32_t h1l = sb + O_H1LO + b1*HB;
        const uint32_t h2h = sb + O_H2HI + b2*HB;
        const uint32_t h2l = sb + O_H2LO + b2*HB;
#pragma unroll
        for (int kc = 0; kc < 4; ++kc)
#pragma unroll
        for (int mi = 0; mi < 2; ++mi) {
            uint32_t base = (uint32_t)(mi*16*144 + kc*32) + a_off;
            uint32_t A1h[4], A1l[4], A2h[4], A2l[4];
            ldsm4(A1h, h1h + base); ldsm4(A1l, h1l + base);
            ldsm4(A2h, h2h + base); ldsm4(A2l, h2l + base);
#pragma unroll
            for (int nj = 0; nj < 2; ++nj) mma_bf16(aL1[mi][nj], A1h, bW[2][kc][nj]);
            if (with_l0) {
#pragma unroll
                for (int nj = 0; nj < 2; ++nj) mma_bf16(aL0[mi][nj], A1h, bW[0][kc][nj]);
            }
#pragma unroll
            for (int nj = 0; nj < 2; ++nj) mma_bf16(aL1[mi][nj], A2h, bW[4][kc][nj]);
            if (with_l0) {
#pragma unroll
                for (int nj = 0; nj < 2; ++nj) mma_bf16(aL0[mi][nj], A1h, bW[1][kc][nj]);
            }
#pragma unroll
            for (int nj = 0; nj < 2; ++nj) mma_bf16(aL1[mi][nj], A1h, bW[3][kc][nj]);
            if (with_l0) {
#pragma unroll
                for (int nj = 0; nj < 2; ++nj) mma_bf16(aL0[mi][nj], A1l, bW[0][kc][nj]);
            }
#pragma unroll
            for (int nj = 0; nj < 2; ++nj) mma_bf16(aL1[mi][nj], A1l, bW[2][kc][nj]);
#pragma unroll
            for (int nj = 0; nj < 2; ++nj) mma_bf16(aL1[mi][nj], A2h, bW[5][kc][nj]);
#pragma unroll
            for (int nj = 0; nj < 2; ++nj) mma_bf16(aL1[mi][nj], A2l, bW[4][kc][nj]);
        }
    };
    auto run_l0 = [&](int b1) {
        const uint32_t h1h = sb + O_H1HI + b1*HB;
        const uint32_t h1l = sb + O_H1LO + b1*HB;
#pragma unroll
        for (int kc = 0; kc < 4; ++kc)
#pragma unroll
        for (int mi = 0; mi < 2; ++mi) {
            uint32_t base = (uint32_t)(mi*16*144 + kc*32) + a_off;
            uint32_t A1h[4], A1l[4];
            ldsm4(A1h, h1h + base); ldsm4(A1l, h1l + base);
#pragma unroll
            for (int nj = 0; nj < 2; ++nj) mma_bf16(aL0[mi][nj], A1h, bW[0][kc][nj]);
#pragma unroll
            for (int nj = 0; nj < 2; ++nj) mma_bf16(aL0[mi][nj], A1h, bW[1][kc][nj]);
#pragma unroll
            for (int nj = 0; nj < 2; ++nj) mma_bf16(aL0[mi][nj], A1l, bW[0][kc][nj]);
        }
    };

    // ---------------- epilogues ----------------
    // acc map: c0=(r,c) c1=(r,c+1) c2=(r+8,c) c3=(r+8,c+1); r = mi*16+ln4, c = nt*16+nj*8+lm4*2
    auto eplg2 = [&](bool want_fc, int bufn) {
        char* d_hi = smb + O_H2HI + bufn*HB;
        char* d_lo = smb + O_H2LO + bufn*HB;
#pragma unroll
        for (int i = 0; i < 4; ++i) { q0v[i] = 0.f; q1v[i] = 0.f; }
#pragma unroll
        for (int mi = 0; mi < 2; ++mi)
#pragma unroll
        for (int nj = 0; nj < 2; ++nj) {
            int c = nt*16 + nj*8 + lm4*2;
            float2 bb = *(const float2*)(smf + O_B1/4 + c);
            const float* a = aL1[mi][nj];
            float v0, v1, v2, v3;
            tanh2(a[0] + bb.x, a[1] + bb.y, v0, v1);
            tanh2(a[2] + bb.x, a[3] + bb.y, v2, v3);
            if (want_fc) {
                float2 f0 = *(const float2*)(smf + O_FCW0/4 + c);
                float2 f1 = *(const float2*)(smf + O_FCW1/4 + c);
                q0v[mi*2+0] += v0*f0.x + v1*f0.y;  q1v[mi*2+0] += v0*f1.x + v1*f1.y;
                q0v[mi*2+1] += v2*f0.x + v3*f0.y;  q1v[mi*2+1] += v2*f1.x + v3*f1.y;
            }
            uint32_t hi0, lo0, hi1, lo1;
            split2(v0, v1, hi0, lo0); split2(v2, v3, hi1, lo1);
            int r0 = mi*16 + ln4;
            *(uint32_t*)(d_hi + r0*144 + c*2)       = hi0;
            *(uint32_t*)(d_lo + r0*144 + c*2)       = lo0;
            *(uint32_t*)(d_hi + (r0+8)*144 + c*2)   = hi1;
            *(uint32_t*)(d_lo + (r0+8)*144 + c*2)   = lo1;
        }
        if (want_fc) {
#pragma unroll
            for (int i = 0; i < 4; ++i) {
                q0v[i] += __shfl_xor_sync(0xffffffffu, q0v[i], 1);
                q0v[i] += __shfl_xor_sync(0xffffffffu, q0v[i], 2);
                q1v[i] += __shfl_xor_sync(0xffffffffu, q1v[i], 1);
                q1v[i] += __shfl_xor_sync(0xffffffffu, q1v[i], 2);
            }
            if (lm4 == 0) {
#pragma unroll
                for (int i = 0; i < 4; ++i) {
                    int row = (i>>1)*16 + (i&1)*8 + ln4;
                    *(float2*)(smb + O_PART + row*32 + nt*8) = make_float2(q0v[i], q1v[i]);
                }
            }
        }
    };
    auto eplg1 = [&](int bufn) {
        char* d_hi = smb + O_H1HI + bufn*HB;
        char* d_lo = smb + O_H1LO + bufn*HB;
#pragma unroll
        for (int mi = 0; mi < 2; ++mi)
#pragma unroll
        for (int nj = 0; nj < 2; ++nj) {
            int c = nt*16 + nj*8 + lm4*2;
            float2 bb = *(const float2*)(smf + O_B0/4 + c);
            float2 w0 = *(const float2*)(smf + O_WX0/4 + c);
            float2 w1 = *(const float2*)(smf + O_WX1/4 + c);
            const float* a = aL0[mi][nj];
            float pA0 = p0v[mi*2+0], pA1 = p1v[mi*2+0];
            float pB0 = p0v[mi*2+1], pB1 = p1v[mi*2+1];
            float v0, v1, v2, v3;
            tanh2(a[0] + bb.x + pA0*w0.x + pA1*w1.x,
                  a[1] + bb.y + pA0*w0.y + pA1*w1.y, v0, v1);
            tanh2(a[2] + bb.x + pB0*w0.x + pB1*w1.x,
                  a[3] + bb.y + pB0*w0.y + pB1*w1.y, v2, v3);
            uint32_t hi0, lo0, hi1, lo1;
            split2(v0, v1, hi0, lo0); split2(v2, v3, hi1, lo1);
            int r0 = mi*16 + ln4;
            *(uint32_t*)(d_hi + r0*144 + c*2)       = hi0;
            *(uint32_t*)(d_lo + r0*144 + c*2)       = lo0;
            *(uint32_t*)(d_hi + (r0+8)*144 + c*2)   = hi1;
            *(uint32_t*)(d_lo + (r0+8)*144 + c*2)   = lo1;
        }
    };
    auto load_x = [&](int t) {
#pragma unroll
        for (int i = 0; i < 4; ++i) {
            int row = (i>>1)*16 + (i&1)*8 + ln4;
            float2 xv = *(const float2*)(smf + O_X/4 + row*22 + 2*t);
            p0v[i] = xv.x; p1v[i] = xv.y;
        }
    };

    // ==================== encoder ====================
    setup_phase(eWhh0, eWih1, eWhh1, eWih0, ebih0, ebhh0, ebih1, ebhh1);
    int c1 = 0, c2 = 0;
    zero_acc();
    load_x(0);
    eplg1(c1);
    __syncthreads();
    for (int t = 0; t < T_HIST; ++t) {
        zero_acc();
        run_mma(c1, c2, t < T_HIST - 1);
        eplg2(false, c2 ^ 1);
        if (t < T_HIST - 1) { load_x(t + 1); eplg1(c1 ^ 1); c1 ^= 1; }
        c2 ^= 1;
        __syncthreads();
    }

    // ==================== decoder ====================
    setup_phase(dWhh0, dWih1, dWhh1, dWih0, dbih0, dbhh0, dbih1, dbhh1);
    const float fcb0 = smf[O_FCB/4], fcb1 = smf[O_FCB/4 + 1];
    zero_acc();
    run_l0(c1);
    load_x(T_HIST - 1);
    eplg1(c1 ^ 1); c1 ^= 1;
    __syncthreads();
    for (int t = 0; t < T_PRED; ++t) {
        zero_acc();
        run_mma(c1, c2, t < T_PRED - 1);
        eplg2(true, c2 ^ 1);
        __syncthreads();
#pragma unroll
        for (int i = 0; i < 4; ++i) {
            int row = (i>>1)*16 + (i&1)*8 + ln4;
            float4 pa = *(const float4*)(smb + O_PART + row*32);
            float4 pb = *(const float4*)(smb + O_PART + row*32 + 16);
            p0v[i] = fcb0 + pa.x + pa.z + pb.x + pb.z;
            p1v[i] = fcb1 + pa.y + pa.w + pb.y + pb.w;
        }
        if (nt == 0 && lm4 == 0) {
#pragma unroll
            for (int i = 0; i < 4; ++i) {
                int row = (i>>1)*16 + (i&1)*8 + ln4;
                float* op = out + (size_t)(bg0 + row) * (T_PRED*2) + t*2;
                op[0] = p0v[i]; op[1] = p1v[i];
            }
        }
        if (t < T_PRED - 1) { eplg1(c1 ^ 1); c1 ^= 1; }
        c2 ^= 1;
        __syncthreads();
    }
}

extern "C" void kernel_launch(void* const* d_in, const int* in_sizes, int n_in,
                              void* d_out, int out_size) {
    (void)in_sizes; (void)n_in; (void)out_size;
    cudaFuncSetAttribute(rnn_mma_kernel,
                         cudaFuncAttributeMaxDynamicSharedMemorySize, SMEM_TOTAL);
    rnn_mma_kernel<<<GRID, NTHR, SMEM_TOTAL>>>(
        (const float*)d_in[0],
        (const float*)d_in[1],  (const float*)d_in[2],  (const float*)d_in[3],  (const float*)d_in[4],
        (const float*)d_in[5],  (const float*)d_in[6],  (const float*)d_in[7],  (const float*)d_in[8],
        (const float*)d_in[9],  (const float*)d_in[10], (const float*)d_in[11], (const float*)d_in[12],
        (const float*)d_in[13], (const float*)d_in[14], (const float*)d_in[15], (const float*)d_in[16],
        (const float*)d_in[17], (const float*)d_in[18],
        (float*)d_out);
}

// round 16
// speedup vs baseline: 1.3112x; 1.3112x over previous
#include <cuda_runtime.h>
#include <cuda_fp16.h>
#include <cstdint>

static constexpr int NTHR = 128;     // 4 warps: nt = wid (16-col group); rows via mi loop
static constexpr int BT = 32;
static constexpr int T_HIST = 11, T_PRED = 80, BATCH = 8192;
static constexpr int GRID = BATCH / BT;   // 256 -> 2 CTAs on most SMs

// ---- smem byte offsets (per CTA) ----
static constexpr int HB     = 4608;       // one 32x72 fp16 buffer (144B rows)
static constexpr int O_H1   = 0;          // 2 buffers
static constexpr int O_H2   = 9216;       // 2 buffers
static constexpr int O_WSTG = 18432;      // staging: hi 9216 + lo 9216 (64x72 fp16 each)
static constexpr int O_X    = 36864;      // 32 x 22 fp32 = 2816
static constexpr int O_B0   = 39680;
static constexpr int O_B1   = 39936;
static constexpr int O_WX0  = 40192;
static constexpr int O_WX1  = 40448;
static constexpr int O_FCW0 = 40704;
static constexpr int O_FCW1 = 40960;
static constexpr int O_FCB  = 41216;
static constexpr int O_PART = 41232;      // 32 rows x 4 groups x float2 = 1024
static constexpr int SMEM_TOTAL = 42256;  // x2 CTAs = 84.5KB << 227KB

__device__ __forceinline__ uint32_t smem_u32(const void* p) {
    uint32_t a;
    asm("{\n\t.reg .u64 t;\n\tcvta.to.shared.u64 t, %1;\n\tcvt.u32.u64 %0, t;\n\t}"
        : "=r"(a) : "l"(p));
    return a;
}
__device__ __forceinline__ void ldsm4(uint32_t r[4], uint32_t a) {
    asm volatile("ldmatrix.sync.aligned.m8n8.x4.shared.b16 {%0,%1,%2,%3}, [%4];"
        : "=r"(r[0]), "=r"(r[1]), "=r"(r[2]), "=r"(r[3]) : "r"(a));
}
__device__ __forceinline__ void mma_f16(float c[4], const uint32_t a[4], const uint32_t b[2]) {
    asm("mma.sync.aligned.m16n8k16.row.col.f32.f16.f16.f32 "
        "{%0,%1,%2,%3},{%4,%5,%6,%7},{%8,%9},{%0,%1,%2,%3};"
        : "+f"(c[0]), "+f"(c[1]), "+f"(c[2]), "+f"(c[3])
        : "r"(a[0]), "r"(a[1]), "r"(a[2]), "r"(a[3]), "r"(b[0]), "r"(b[1]));
}
__device__ __forceinline__ float tanh_fast(float x) {
    float t = __expf(2.0f * x);
    return 1.0f - __fdividef(2.0f, t + 1.0f);
}
// pack two fp32 -> one fp16x2 word (lo = f0, hi = f1)
__device__ __forceinline__ uint32_t pack_h2(float f0, float f1) {
    uint32_t r;
    asm("cvt.rn.f16x2.f32 %0, %1, %2;" : "=r"(r) : "f"(f1), "f"(f0));
    return r;
}

__global__ __launch_bounds__(NTHR, 2)
void rnn_mma_kernel(const float* __restrict__ x,
    const float* __restrict__ eWih0, const float* __restrict__ eWhh0,
    const float* __restrict__ ebih0, const float* __restrict__ ebhh0,
    const float* __restrict__ eWih1, const float* __restrict__ eWhh1,
    const float* __restrict__ ebih1, const float* __restrict__ ebhh1,
    const float* __restrict__ dWih0, const float* __restrict__ dWhh0,
    const float* __restrict__ dbih0, const float* __restrict__ dbhh0,
    const float* __restrict__ dWih1, const float* __restrict__ dWhh1,
    const float* __restrict__ dbih1, const float* __restrict__ dbhh1,
    const float* __restrict__ fcW, const float* __restrict__ fcb,
    float* __restrict__ out)
{
    extern __shared__ __align__(128) char smb[];
    float* smf = (float*)smb;
    const uint32_t sb = smem_u32(smb);
    const int tid  = threadIdx.x;
    const int wid  = tid >> 5, lane = tid & 31;
    const int nt   = wid;                // col group: cols nt*16 .. +15
    const int ln4  = lane >> 2, lm4 = lane & 3;
    const int bg0  = blockIdx.x * BT;
    const uint32_t a_off = (uint32_t)((lane & 15) * 144 + (lane >> 4) * 16);

    // persistent B frags: [0]=W0hi [1]=W0lo [2]=W1hi [3]=W1lo [4]=W2hi [5]=W2lo
    uint32_t bW[6][4][2][2];
    float aL1[2][2][4], aL0[2][2][4];    // [mi][nj][e]
    float q0v[4], q1v[4], p0v[4], p1v[4];

    auto zero_acc = [&]() {
#pragma unroll
        for (int mi = 0; mi < 2; ++mi)
#pragma unroll
        for (int nj = 0; nj < 2; ++nj)
#pragma unroll
        for (int e = 0; e < 4; ++e) { aL1[mi][nj][e] = 0.f; aL0[mi][nj][e] = 0.f; }
    };

    // ---------------- one-time init ----------------
    for (int i = tid; i < 4608; i += NTHR) ((uint32_t*)smb)[i] = 0u;   // zero h buffers (18432B)
    for (int i = tid; i < BT * 2 * T_HIST; i += NTHR)
        smf[O_X/4 + i] = x[(size_t)bg0 * (2*T_HIST) + i];
    if (tid < 64) { smf[O_FCW0/4 + tid] = fcW[tid]; smf[O_FCW1/4 + tid] = fcW[64 + tid]; }
    if (tid < 2)  { smf[O_FCB/4 + tid] = fcb[tid]; }

    // ---------------- phase setup ----------------
    auto setup_phase = [&](const float* W0, const float* W1, const float* W2,
                           const float* Wih0, const float* bih0, const float* bhh0,
                           const float* bih1, const float* bhh1) {
        const float* Ws[3] = {W0, W1, W2};
        unsigned short* sh = (unsigned short*)(smb + O_WSTG);
        unsigned short* sl = sh + 4608;
#pragma unroll
        for (int w = 0; w < 3; ++w) {
            __syncthreads();
            for (int idx = tid; idx < 4096; idx += NTHR) {
                int k = idx >> 6, j = idx & 63;
                float wv = Ws[w][j*64 + k];            // WT[k][j] = W[j][k]
                __half wh = __float2half_rn(wv);
                __half wl = __float2half_rn(wv - __half2float(wh));
                sh[k*72 + j] = *(unsigned short*)&wh;
                sl[k*72 + j] = *(unsigned short*)&wl;
            }
            __syncthreads();
            int n = nt*16 + ln4;
#pragma unroll
            for (int kc = 0; kc < 4; ++kc)
#pragma unroll
            for (int nj = 0; nj < 2; ++nj) {
                int nn = n + nj*8;
                int k0 = kc*16 + lm4*2;
                bW[2*w][kc][nj][0]   = (uint32_t)sh[k0*72+nn]     | ((uint32_t)sh[(k0+1)*72+nn] << 16);
                bW[2*w][kc][nj][1]   = (uint32_t)sh[(k0+8)*72+nn] | ((uint32_t)sh[(k0+9)*72+nn] << 16);
                bW[2*w+1][kc][nj][0] = (uint32_t)sl[k0*72+nn]     | ((uint32_t)sl[(k0+1)*72+nn] << 16);
                bW[2*w+1][kc][nj][1] = (uint32_t)sl[(k0+8)*72+nn] | ((uint32_t)sl[(k0+9)*72+nn] << 16);
            }
        }
        if (tid < 64) {
            smf[O_WX0/4 + tid] = Wih0[tid*2];
            smf[O_WX1/4 + tid] = Wih0[tid*2 + 1];
            smf[O_B0/4  + tid] = bih0[tid] + bhh0[tid];
            smf[O_B1/4  + tid] = bih1[tid] + bhh1[tid];
        }
        __syncthreads();
    };

    // ---------------- MMA phases (6 terms fused, or 2 for l0-only) ----------------
    auto run_mma = [&](int b1, int b2, bool with_l0) {
        const uint32_t h1p = sb + O_H1 + b1*HB;
        const uint32_t h2p = sb + O_H2 + b2*HB;
#pragma unroll
        for (int kc = 0; kc < 4; ++kc)
#pragma unroll
        for (int mi = 0; mi < 2; ++mi) {
            uint32_t base = (uint32_t)(mi*16*144 + kc*32) + a_off;
            uint32_t A1[4], A2[4];
            ldsm4(A1, h1p + base);
            ldsm4(A2, h2p + base);
#pragma unroll
            for (int nj = 0; nj < 2; ++nj) mma_f16(aL1[mi][nj], A1, bW[2][kc][nj]);
            if (with_l0) {
#pragma unroll
                for (int nj = 0; nj < 2; ++nj) mma_f16(aL0[mi][nj], A1, bW[0][kc][nj]);
            }
#pragma unroll
            for (int nj = 0; nj < 2; ++nj) mma_f16(aL1[mi][nj], A2, bW[4][kc][nj]);
            if (with_l0) {
#pragma unroll
                for (int nj = 0; nj < 2; ++nj) mma_f16(aL0[mi][nj], A1, bW[1][kc][nj]);
            }
#pragma unroll
            for (int nj = 0; nj < 2; ++nj) mma_f16(aL1[mi][nj], A1, bW[3][kc][nj]);
#pragma unroll
            for (int nj = 0; nj < 2; ++nj) mma_f16(aL1[mi][nj], A2, bW[5][kc][nj]);
        }
    };
    auto run_l0 = [&](int b1) {
        const uint32_t h1p = sb + O_H1 + b1*HB;
#pragma unroll
        for (int kc = 0; kc < 4; ++kc)
#pragma unroll
        for (int mi = 0; mi < 2; ++mi) {
            uint32_t base = (uint32_t)(mi*16*144 + kc*32) + a_off;
            uint32_t A1[4];
            ldsm4(A1, h1p + base);
#pragma unroll
            for (int nj = 0; nj < 2; ++nj) mma_f16(aL0[mi][nj], A1, bW[0][kc][nj]);
#pragma unroll
            for (int nj = 0; nj < 2; ++nj) mma_f16(aL0[mi][nj], A1, bW[1][kc][nj]);
        }
    };

    // ---------------- epilogues ----------------
    // acc map: c0=(r,c) c1=(r,c+1) c2=(r+8,c) c3=(r+8,c+1); r = mi*16+ln4, c = nt*16+nj*8+lm4*2
    auto eplg2 = [&](bool want_fc, int bufn) {
        char* dh = smb + O_H2 + bufn*HB;
#pragma unroll
        for (int i = 0; i < 4; ++i) { q0v[i] = 0.f; q1v[i] = 0.f; }
#pragma unroll
        for (int mi = 0; mi < 2; ++mi)
#pragma unroll
        for (int nj = 0; nj < 2; ++nj) {
            int c = nt*16 + nj*8 + lm4*2;
            float2 bb = *(const float2*)(smf + O_B1/4 + c);
            const float* a = aL1[mi][nj];
            float v0 = tanh_fast(a[0] + bb.x), v1 = tanh_fast(a[1] + bb.y);
            float v2 = tanh_fast(a[2] + bb.x), v3 = tanh_fast(a[3] + bb.y);
            if (want_fc) {
                float2 f0 = *(const float2*)(smf + O_FCW0/4 + c);
                float2 f1 = *(const float2*)(smf + O_FCW1/4 + c);
                q0v[mi*2+0] += v0*f0.x + v1*f0.y;  q1v[mi*2+0] += v0*f1.x + v1*f1.y;
                q0v[mi*2+1] += v2*f0.x + v3*f0.y;  q1v[mi*2+1] += v2*f1.x + v3*f1.y;
            }
            int r0 = mi*16 + ln4;
            *(uint32_t*)(dh + r0*144 + c*2)     = pack_h2(v0, v1);
            *(uint32_t*)(dh + (r0+8)*144 + c*2) = pack_h2(v2, v3);
        }
        if (want_fc) {
#pragma unroll
            for (int i = 0; i < 4; ++i) {
                q0v[i] += __shfl_xor_sync(0xffffffffu, q0v[i], 1);
                q0v[i] += __shfl_xor_sync(0xffffffffu, q0v[i], 2);
                q1v[i] += __shfl_xor_sync(0xffffffffu, q1v[i], 1);
                q1v[i] += __shfl_xor_sync(0xffffffffu, q1v[i], 2);
            }
            if (lm4 == 0) {
#pragma unroll
                for (int i = 0; i < 4; ++i) {
                    int row = (i>>1)*16 + (i&1)*8 + ln4;
                    *(float2*)(smb + O_PART + row*32 + nt*8) = make_float2(q0v[i], q1v[i]);
                }
            }
        }
    };
    auto eplg1 = [&](int bufn) {
        char* dh = smb + O_H1 + bufn*HB;
#pragma unroll
        for (int mi = 0; mi < 2; ++mi)
#pragma unroll
        for (int nj = 0; nj < 2; ++nj) {
            int c = nt*16 + nj*8 + lm4*2;
            float2 bb = *(const float2*)(smf + O_B0/4 + c);
            float2 w0 = *(const float2*)(smf + O_WX0/4 + c);
            float2 w1 = *(const float2*)(smf + O_WX1/4 + c);
            const float* a = aL0[mi][nj];
            float pA0 = p0v[mi*2+0], pA1 = p1v[mi*2+0];
            float pB0 = p0v[mi*2+1], pB1 = p1v[mi*2+1];
            float v0 = tanh_fast(a[0] + bb.x + pA0*w0.x + pA1*w1.x);
            float v1 = tanh_fast(a[1] + bb.y + pA0*w0.y + pA1*w1.y);
            float v2 = tanh_fast(a[2] + bb.x + pB0*w0.x + pB1*w1.x);
            float v3 = tanh_fast(a[3] + bb.y + pB0*w0.y + pB1*w1.y);
            int r0 = mi*16 + ln4;
            *(uint32_t*)(dh + r0*144 + c*2)     = pack_h2(v0, v1);
            *(uint32_t*)(dh + (r0+8)*144 + c*2) = pack_h2(v2, v3);
        }
    };
    auto load_x = [&](int t) {
#pragma unroll
        for (int i = 0; i < 4; ++i) {
            int row = (i>>1)*16 + (i&1)*8 + ln4;
            float2 xv = *(const float2*)(smf + O_X/4 + row*22 + 2*t);
            p0v[i] = xv.x; p1v[i] = xv.y;
        }
    };

    // ==================== encoder ====================
    setup_phase(eWhh0, eWih1, eWhh1, eWih0, ebih0, ebhh0, ebih1, ebhh1);
    int c1 = 0, c2 = 0;
    zero_acc();
    load_x(0);
    eplg1(c1);
    __syncthreads();
    for (int t = 0; t < T_HIST; ++t) {
        zero_acc();
        run_mma(c1, c2, t < T_HIST - 1);
        eplg2(false, c2 ^ 1);
        if (t < T_HIST - 1) { load_x(t + 1); eplg1(c1 ^ 1); c1 ^= 1; }
        c2 ^= 1;
        __syncthreads();
    }

    // ==================== decoder ====================
    setup_phase(dWhh0, dWih1, dWhh1, dWih0, dbih0, dbhh0, dbih1, dbhh1);
    const float fcb0 = smf[O_FCB/4], fcb1 = smf[O_FCB/4 + 1];
    zero_acc();
    run_l0(c1);
    load_x(T_HIST - 1);
    eplg1(c1 ^ 1); c1 ^= 1;
    __syncthreads();
    for (int t = 0; t < T_PRED; ++t) {
        zero_acc();
        run_mma(c1, c2, t < T_PRED - 1);
        eplg2(true, c2 ^ 1);
        __syncthreads();
#pragma unroll
        for (int i = 0; i < 4; ++i) {
            int row = (i>>1)*16 + (i&1)*8 + ln4;
            float4 pa = *(const float4*)(smb + O_PART + row*32);
            float4 pb = *(const float4*)(smb + O_PART + row*32 + 16);
            p0v[i] = fcb0 + pa.x + pa.z + pb.x + pb.z;
            p1v[i] = fcb1 + pa.y + pa.w + pb.y + pb.w;
        }
        if (nt == 0 && lm4 == 0) {
#pragma unroll
            for (int i = 0; i < 4; ++i) {
                int row = (i>>1)*16 + (i&1)*8 + ln4;
                float* op = out + (size_t)(bg0 + row) * (T_PRED*2) + t*2;
                op[0] = p0v[i]; op[1] = p1v[i];
            }
        }
        if (t < T_PRED - 1) { eplg1(c1 ^ 1); c1 ^= 1; }
        c2 ^= 1;
        __syncthreads();
    }
}

extern "C" void kernel_launch(void* const* d_in, const int* in_sizes, int n_in,
                              void* d_out, int out_size) {
    (void)in_sizes; (void)n_in; (void)out_size;
    cudaFuncSetAttribute(rnn_mma_kernel,
                         cudaFuncAttributeMaxDynamicSharedMemorySize, SMEM_TOTAL);
    rnn_mma_kernel<<<GRID, NTHR, SMEM_TOTAL>>>(
        (const float*)d_in[0],
        (const float*)d_in[1],  (const float*)d_in[2],  (const float*)d_in[3],  (const float*)d_in[4],
        (const float*)d_in[5],  (const float*)d_in[6],  (const float*)d_in[7],  (const float*)d_in[8],
        (const float*)d_in[9],  (const float*)d_in[10], (const float*)d_in[11], (const float*)d_in[12],
        (const float*)d_in[13], (const float*)d_in[14], (const float*)d_in[15], (const float*)d_in[16],
        (const float*)d_in[17], (const float*)d_in[18],
        (float*)d_out);
}

// round 17
// speedup vs baseline: 1.4867x; 1.1339x over previous
#include <cuda_runtime.h>
#include <cuda_fp16.h>
#include <cstdint>

static constexpr int NTHR = 128;     // 4 warps: nt = wid (16-col group); rows via mi loop
static constexpr int BT = 32;
static constexpr int T_HIST = 11, T_PRED = 80, BATCH = 8192;
static constexpr int GRID = BATCH / BT;   // 256 -> 2 CTAs on most SMs

// ---- smem byte offsets (per CTA) ----
static constexpr int HB     = 4608;       // one 32x72 fp16 buffer (144B rows)
static constexpr int O_H1   = 0;          // 2 buffers
static constexpr int O_H2   = 9216;       // 2 buffers
static constexpr int O_WSTG = 18432;      // staging: hi 9216 + lo 9216 (64x72 fp16 each)
static constexpr int O_X    = 36864;      // 32 x 22 fp32 = 2816
static constexpr int O_B0   = 39680;
static constexpr int O_B1   = 39936;
static constexpr int O_WX0  = 40192;
static constexpr int O_WX1  = 40448;
static constexpr int O_FCW0 = 40704;
static constexpr int O_FCW1 = 40960;
static constexpr int O_FCB  = 41216;
static constexpr int O_PART = 41232;      // 32 rows x 4 groups x float2 = 1024
static constexpr int SMEM_TOTAL = 42256;  // x2 CTAs = 84.5KB << 227KB

__device__ __forceinline__ uint32_t smem_u32(const void* p) {
    uint32_t a;
    asm("{\n\t.reg .u64 t;\n\tcvta.to.shared.u64 t, %1;\n\tcvt.u32.u64 %0, t;\n\t}"
        : "=r"(a) : "l"(p));
    return a;
}
__device__ __forceinline__ void ldsm4(uint32_t r[4], uint32_t a) {
    asm volatile("ldmatrix.sync.aligned.m8n8.x4.shared.b16 {%0,%1,%2,%3}, [%4];"
        : "=r"(r[0]), "=r"(r[1]), "=r"(r[2]), "=r"(r[3]) : "r"(a));
}
__device__ __forceinline__ void mma_f16(float c[4], const uint32_t a[4], const uint32_t b[2]) {
    asm("mma.sync.aligned.m16n8k16.row.col.f32.f16.f16.f32 "
        "{%0,%1,%2,%3},{%4,%5,%6,%7},{%8,%9},{%0,%1,%2,%3};"
        : "+f"(c[0]), "+f"(c[1]), "+f"(c[2]), "+f"(c[3])
        : "r"(a[0]), "r"(a[1]), "r"(a[2]), "r"(a[3]), "r"(b[0]), "r"(b[1]));
}
// hardware tanh: single MUFU op (sm_75+). Abs err ~2^-10.5 worst case — same
// order as the fp16 h-quantization this kernel already carries per step.
__device__ __forceinline__ float tanh_hw(float x) {
    float r;
    asm("tanh.approx.f32 %0, %1;" : "=f"(r) : "f"(x));
    return r;
}
// pack two fp32 -> one fp16x2 word (lo = f0, hi = f1)
__device__ __forceinline__ uint32_t pack_h2(float f0, float f1) {
    uint32_t r;
    asm("cvt.rn.f16x2.f32 %0, %1, %2;" : "=r"(r) : "f"(f1), "f"(f0));
    return r;
}

__global__ __launch_bounds__(NTHR, 2)
void rnn_mma_kernel(const float* __restrict__ x,
    const float* __restrict__ eWih0, const float* __restrict__ eWhh0,
    const float* __restrict__ ebih0, const float* __restrict__ ebhh0,
    const float* __restrict__ eWih1, const float* __restrict__ eWhh1,
    const float* __restrict__ ebih1, const float* __restrict__ ebhh1,
    const float* __restrict__ dWih0, const float* __restrict__ dWhh0,
    const float* __restrict__ dbih0, const float* __restrict__ dbhh0,
    const float* __restrict__ dWih1, const float* __restrict__ dWhh1,
    const float* __restrict__ dbih1, const float* __restrict__ dbhh1,
    const float* __restrict__ fcW, const float* __restrict__ fcb,
    float* __restrict__ out)
{
    extern __shared__ __align__(128) char smb[];
    float* smf = (float*)smb;
    const uint32_t sb = smem_u32(smb);
    const int tid  = threadIdx.x;
    const int wid  = tid >> 5, lane = tid & 31;
    const int nt   = wid;                // col group: cols nt*16 .. +15
    const int ln4  = lane >> 2, lm4 = lane & 3;
    const int bg0  = blockIdx.x * BT;
    const uint32_t a_off = (uint32_t)((lane & 15) * 144 + (lane >> 4) * 16);

    // persistent B frags: [0]=W0hi [1]=W0lo [2]=W1hi [3]=W1lo [4]=W2hi [5]=W2lo
    uint32_t bW[6][4][2][2];
    float aL1[2][2][4], aL0[2][2][4];    // [mi][nj][e]
    float q0v[4], q1v[4], p0v[4], p1v[4];

    auto zero_acc = [&]() {
#pragma unroll
        for (int mi = 0; mi < 2; ++mi)
#pragma unroll
        for (int nj = 0; nj < 2; ++nj)
#pragma unroll
        for (int e = 0; e < 4; ++e) { aL1[mi][nj][e] = 0.f; aL0[mi][nj][e] = 0.f; }
    };

    // ---------------- one-time init ----------------
    for (int i = tid; i < 4608; i += NTHR) ((uint32_t*)smb)[i] = 0u;   // zero h buffers
    for (int i = tid; i < BT * 2 * T_HIST; i += NTHR)
        smf[O_X/4 + i] = x[(size_t)bg0 * (2*T_HIST) + i];
    if (tid < 64) { smf[O_FCW0/4 + tid] = fcW[tid]; smf[O_FCW1/4 + tid] = fcW[64 + tid]; }
    if (tid < 2)  { smf[O_FCB/4 + tid] = fcb[tid]; }

    // ---------------- phase setup ----------------
    auto setup_phase = [&](const float* W0, const float* W1, const float* W2,
                           const float* Wih0, const float* bih0, const float* bhh0,
                           const float* bih1, const float* bhh1) {
        const float* Ws[3] = {W0, W1, W2};
        unsigned short* sh = (unsigned short*)(smb + O_WSTG);
        unsigned short* sl = sh + 4608;
#pragma unroll
        for (int w = 0; w < 3; ++w) {
            __syncthreads();
            for (int idx = tid; idx < 4096; idx += NTHR) {
                int k = idx >> 6, j = idx & 63;
                float wv = Ws[w][j*64 + k];            // WT[k][j] = W[j][k]
                __half wh = __float2half_rn(wv);
                __half wl = __float2half_rn(wv - __half2float(wh));
                sh[k*72 + j] = *(unsigned short*)&wh;
                sl[k*72 + j] = *(unsigned short*)&wl;
            }
            __syncthreads();
            int n = nt*16 + ln4;
#pragma unroll
            for (int kc = 0; kc < 4; ++kc)
#pragma unroll
            for (int nj = 0; nj < 2; ++nj) {
                int nn = n + nj*8;
                int k0 = kc*16 + lm4*2;
                bW[2*w][kc][nj][0]   = (uint32_t)sh[k0*72+nn]     | ((uint32_t)sh[(k0+1)*72+nn] << 16);
                bW[2*w][kc][nj][1]   = (uint32_t)sh[(k0+8)*72+nn] | ((uint32_t)sh[(k0+9)*72+nn] << 16);
                bW[2*w+1][kc][nj][0] = (uint32_t)sl[k0*72+nn]     | ((uint32_t)sl[(k0+1)*72+nn] << 16);
                bW[2*w+1][kc][nj][1] = (uint32_t)sl[(k0+8)*72+nn] | ((uint32_t)sl[(k0+9)*72+nn] << 16);
            }
        }
        if (tid < 64) {
            smf[O_WX0/4 + tid] = Wih0[tid*2];
            smf[O_WX1/4 + tid] = Wih0[tid*2 + 1];
            smf[O_B0/4  + tid] = bih0[tid] + bhh0[tid];
            smf[O_B1/4  + tid] = bih1[tid] + bhh1[tid];
        }
        __syncthreads();
    };

    // ---------------- MMA phases (6 terms fused, or 2 for l0-only) ----------------
    auto run_mma = [&](int b1, int b2, bool with_l0) {
        const uint32_t h1p = sb + O_H1 + b1*HB;
        const uint32_t h2p = sb + O_H2 + b2*HB;
#pragma unroll
        for (int kc = 0; kc < 4; ++kc)
#pragma unroll
        for (int mi = 0; mi < 2; ++mi) {
            uint32_t base = (uint32_t)(mi*16*144 + kc*32) + a_off;
            uint32_t A1[4], A2[4];
            ldsm4(A1, h1p + base);
            ldsm4(A2, h2p + base);
#pragma unroll
            for (int nj = 0; nj < 2; ++nj) mma_f16(aL1[mi][nj], A1, bW[2][kc][nj]);
            if (with_l0) {
#pragma unroll
                for (int nj = 0; nj < 2; ++nj) mma_f16(aL0[mi][nj], A1, bW[0][kc][nj]);
            }
#pragma unroll
            for (int nj = 0; nj < 2; ++nj) mma_f16(aL1[mi][nj], A2, bW[4][kc][nj]);
            if (with_l0) {
#pragma unroll
                for (int nj = 0; nj < 2; ++nj) mma_f16(aL0[mi][nj], A1, bW[1][kc][nj]);
            }
#pragma unroll
            for (int nj = 0; nj < 2; ++nj) mma_f16(aL1[mi][nj], A1, bW[3][kc][nj]);
#pragma unroll
            for (int nj = 0; nj < 2; ++nj) mma_f16(aL1[mi][nj], A2, bW[5][kc][nj]);
        }
    };
    auto run_l0 = [&](int b1) {
        const uint32_t h1p = sb + O_H1 + b1*HB;
#pragma unroll
        for (int kc = 0; kc < 4; ++kc)
#pragma unroll
        for (int mi = 0; mi < 2; ++mi) {
            uint32_t base = (uint32_t)(mi*16*144 + kc*32) + a_off;
            uint32_t A1[4];
            ldsm4(A1, h1p + base);
#pragma unroll
            for (int nj = 0; nj < 2; ++nj) mma_f16(aL0[mi][nj], A1, bW[0][kc][nj]);
#pragma unroll
            for (int nj = 0; nj < 2; ++nj) mma_f16(aL0[mi][nj], A1, bW[1][kc][nj]);
        }
    };

    // ---------------- epilogues ----------------
    // acc map: c0=(r,c) c1=(r,c+1) c2=(r+8,c) c3=(r+8,c+1); r = mi*16+ln4, c = nt*16+nj*8+lm4*2
    auto eplg2 = [&](bool want_fc, int bufn) {
        char* dh = smb + O_H2 + bufn*HB;
#pragma unroll
        for (int i = 0; i < 4; ++i) { q0v[i] = 0.f; q1v[i] = 0.f; }
#pragma unroll
        for (int mi = 0; mi < 2; ++mi)
#pragma unroll
        for (int nj = 0; nj < 2; ++nj) {
            int c = nt*16 + nj*8 + lm4*2;
            float2 bb = *(const float2*)(smf + O_B1/4 + c);
            const float* a = aL1[mi][nj];
            float v0 = tanh_hw(a[0] + bb.x), v1 = tanh_hw(a[1] + bb.y);
            float v2 = tanh_hw(a[2] + bb.x), v3 = tanh_hw(a[3] + bb.y);
            if (want_fc) {
                float2 f0 = *(const float2*)(smf + O_FCW0/4 + c);
                float2 f1 = *(const float2*)(smf + O_FCW1/4 + c);
                q0v[mi*2+0] += v0*f0.x + v1*f0.y;  q1v[mi*2+0] += v0*f1.x + v1*f1.y;
                q0v[mi*2+1] += v2*f0.x + v3*f0.y;  q1v[mi*2+1] += v2*f1.x + v3*f1.y;
            }
            int r0 = mi*16 + ln4;
            *(uint32_t*)(dh + r0*144 + c*2)     = pack_h2(v0, v1);
            *(uint32_t*)(dh + (r0+8)*144 + c*2) = pack_h2(v2, v3);
        }
        if (want_fc) {
#pragma unroll
            for (int i = 0; i < 4; ++i) {
                q0v[i] += __shfl_xor_sync(0xffffffffu, q0v[i], 1);
                q0v[i] += __shfl_xor_sync(0xffffffffu, q0v[i], 2);
                q1v[i] += __shfl_xor_sync(0xffffffffu, q1v[i], 1);
                q1v[i] += __shfl_xor_sync(0xffffffffu, q1v[i], 2);
            }
            if (lm4 == 0) {
#pragma unroll
                for (int i = 0; i < 4; ++i) {
                    int row = (i>>1)*16 + (i&1)*8 + ln4;
                    *(float2*)(smb + O_PART + row*32 + nt*8) = make_float2(q0v[i], q1v[i]);
                }
            }
        }
    };
    auto eplg1 = [&](int bufn) {
        char* dh = smb + O_H1 + bufn*HB;
#pragma unroll
        for (int mi = 0; mi < 2; ++mi)
#pragma unroll
        for (int nj = 0; nj < 2; ++nj) {
            int c = nt*16 + nj*8 + lm4*2;
            float2 bb = *(const float2*)(smf + O_B0/4 + c);
            float2 w0 = *(const float2*)(smf + O_WX0/4 + c);
            float2 w1 = *(const float2*)(smf + O_WX1/4 + c);
            const float* a = aL0[mi][nj];
            float pA0 = p0v[mi*2+0], pA1 = p1v[mi*2+0];
            float pB0 = p0v[mi*2+1], pB1 = p1v[mi*2+1];
            float v0 = tanh_hw(a[0] + bb.x + pA0*w0.x + pA1*w1.x);
            float v1 = tanh_hw(a[1] + bb.y + pA0*w0.y + pA1*w1.y);
            float v2 = tanh_hw(a[2] + bb.x + pB0*w0.x + pB1*w1.x);
            float v3 = tanh_hw(a[3] + bb.y + pB0*w0.y + pB1*w1.y);
            int r0 = mi*16 + ln4;
            *(uint32_t*)(dh + r0*144 + c*2)     = pack_h2(v0, v1);
            *(uint32_t*)(dh + (r0+8)*144 + c*2) = pack_h2(v2, v3);
        }
    };
    auto load_x = [&](int t) {
#pragma unroll
        for (int i = 0; i < 4; ++i) {
            int row = (i>>1)*16 + (i&1)*8 + ln4;
            float2 xv = *(const float2*)(smf + O_X/4 + row*22 + 2*t);
            p0v[i] = xv.x; p1v[i] = xv.y;
        }
    };

    // ==================== encoder ====================
    setup_phase(eWhh0, eWih1, eWhh1, eWih0, ebih0, ebhh0, ebih1, ebhh1);
    int c1 = 0, c2 = 0;
    zero_acc();
    load_x(0);
    eplg1(c1);
    __syncthreads();
    for (int t = 0; t < T_HIST; ++t) {
        zero_acc();
        run_mma(c1, c2, t < T_HIST - 1);
        eplg2(false, c2 ^ 1);
        if (t < T_HIST - 1) { load_x(t + 1); eplg1(c1 ^ 1); c1 ^= 1; }
        c2 ^= 1;
        __syncthreads();
    }

    // ==================== decoder ====================
    setup_phase(dWhh0, dWih1, dWhh1, dWih0, dbih0, dbhh0, dbih1, dbhh1);
    const float fcb0 = smf[O_FCB/4], fcb1 = smf[O_FCB/4 + 1];
    zero_acc();
    run_l0(c1);
    load_x(T_HIST - 1);
    eplg1(c1 ^ 1); c1 ^= 1;
    __syncthreads();
    for (int t = 0; t < T_PRED; ++t) {
        zero_acc();
        run_mma(c1, c2, t < T_PRED - 1);
        eplg2(true, c2 ^ 1);
        __syncthreads();
#pragma unroll
        for (int i = 0; i < 4; ++i) {
            int row = (i>>1)*16 + (i&1)*8 + ln4;
            float4 pa = *(const float4*)(smb + O_PART + row*32);
            float4 pb = *(const float4*)(smb + O_PART + row*32 + 16);
            p0v[i] = fcb0 + pa.x + pa.z + pb.x + pb.z;
            p1v[i] = fcb1 + pa.y + pa.w + pb.y + pb.w;
        }
        if (nt == 0 && lm4 == 0) {
#pragma unroll
            for (int i = 0; i < 4; ++i) {
                int row = (i>>1)*16 + (i&1)*8 + ln4;
                float* op = out + (size_t)(bg0 + row) * (T_PRED*2) + t*2;
                op[0] = p0v[i]; op[1] = p1v[i];
            }
        }
        if (t < T_PRED - 1) { eplg1(c1 ^ 1); c1 ^= 1; }
        c2 ^= 1;
        __syncthreads();
    }
}

extern "C" void kernel_launch(void* const* d_in, const int* in_sizes, int n_in,
                              void* d_out, int out_size) {
    (void)in_sizes; (void)n_in; (void)out_size;
    cudaFuncSetAttribute(rnn_mma_kernel,
                         cudaFuncAttributeMaxDynamicSharedMemorySize, SMEM_TOTAL);
    rnn_mma_kernel<<<GRID, NTHR, SMEM_TOTAL>>>(
        (const float*)d_in[0],
        (const float*)d_in[1],  (const float*)d_in[2],  (const float*)d_in[3],  (const float*)d_in[4],
        (const float*)d_in[5],  (const float*)d_in[6],  (const float*)d_in[7],  (const float*)d_in[8],
        (const float*)d_in[9],  (const float*)d_in[10], (const float*)d_in[11], (const float*)d_in[12],
        (const float*)d_in[13], (const float*)d_in[14], (const float*)d_in[15], (const float*)d_in[16],
        (const float*)d_in[17], (const float*)d_in[18],
        (float*)d_out);
}